// round 3
// baseline (speedup 1.0000x reference)
#include <cuda_runtime.h>
#include <cuda_bf16.h>
#include <math.h>

#define NN 100000
#define EE 1600000
#define RR 6
#define DIN 128
#define HH 64

// ---------------- scratch (static device memory; no allocation at runtime) ----------------
static __device__ int   g_deg[RR * NN];
static __device__ float g_dis[RR * NN];
static __device__ int   g_rowptr[RR * (NN + 1)];
static __device__ int   g_next[RR * NN];
static __device__ int2  g_edata[(size_t)RR * EE];
static __device__ float g_y[(size_t)RR * NN * 192];     // P|Q|S projections per relation
static __device__ float g_w[(size_t)RR * NN * HH];      // intermediate w = Q + 2*lhat(S)
static __device__ float g_h[(size_t)RR * NN * HH];      // layer-1 output h1
static __device__ float g_stack[(size_t)NN * RR * HH];  // final per-relation embeddings

// ---------------- CSR build ----------------
__global__ void k_zero() {
    int id = blockIdx.x * blockDim.x + threadIdx.x;
    if (id < RR * NN) { g_deg[id] = 0; g_next[id] = 0; }
}

__global__ void k_count(const int* __restrict__ ei) {
    int id = blockIdx.x * blockDim.x + threadIdx.x;
    if (id >= RR * EE) return;
    int r = id / EE, e = id - r * EE;
    int src = ei[(size_t)(r * 2) * EE + e];
    int dst = ei[(size_t)(r * 2 + 1) * EE + e];
    atomicAdd(&g_deg[r * NN + src], 1);
    atomicAdd(&g_next[r * NN + dst], 1);   // g_next holds in-degree counts for now
}

// one block per relation: exclusive scan of in-degree counts -> rowptr, init g_next = rowptr.
// Also computes g_dis from out-degree (fused former k_dis).
__global__ void k_scan() {
    __shared__ int ssum[1024];
    const int CH = (NN + 1023) / 1024;   // 98
    int r = blockIdx.x;
    int t = threadIdx.x;
    int base = r * NN;
    int st = t * CH;
    int local = 0;
    for (int i = 0; i < CH; i++) {
        int idx = st + i;
        if (idx < NN) local += g_next[base + idx];
    }
    ssum[t] = local;
    __syncthreads();
    for (int off = 1; off < 1024; off <<= 1) {
        int v = (t >= off) ? ssum[t - off] : 0;
        __syncthreads();
        ssum[t] += v;
        __syncthreads();
    }
    int run = ssum[t] - local;  // exclusive prefix
    for (int i = 0; i < CH; i++) {
        int idx = st + i;
        if (idx < NN) {
            int c = g_next[base + idx];
            g_rowptr[r * (NN + 1) + idx] = run;
            g_next[base + idx] = run;
            run += c;
            int d = g_deg[base + idx];
            g_dis[base + idx] = (d > 0) ? rsqrtf((float)d) : 0.0f;
        }
    }
    if (t == 1023) g_rowptr[r * (NN + 1) + NN] = ssum[1023];
}

__global__ void k_scatter(const int* __restrict__ ei) {
    int id = blockIdx.x * blockDim.x + threadIdx.x;
    if (id >= RR * EE) return;
    int r = id / EE, e = id - r * EE;
    int src = ei[(size_t)(r * 2) * EE + e];
    int dst = ei[(size_t)(r * 2 + 1) * EE + e];
    int pos = atomicAdd(&g_next[r * NN + dst], 1);
    float nv = -g_dis[r * NN + src] * g_dis[r * NN + dst];
    g_edata[(size_t)r * EE + pos] = make_int2(src, __float_as_int(nv));
}

// ---------------- fused GEMM: [N,FIN] @ [W0-W2 | W1 | W2][FIN,192] -> g_y ----------------
// Weight combination done on the fly from the original cheb weights [R,3,FIN,64].
// Inner loop uses packed fma.rn.f32x2 (FFMA2, b64 regs) for 2x fp32 FMA throughput.
template <int FIN, bool XIN>
__global__ void __launch_bounds__(128) k_gemm(const float* __restrict__ xin,
                                              const float* __restrict__ Wsrc) {
    const int r = blockIdx.y;
    const int row0 = blockIdx.x * 64;
    const float* A = XIN ? xin : (g_h + (size_t)r * NN * HH);
    const float* Wr = Wsrc + (size_t)r * 3 * FIN * 64;
    float* O = g_y + (size_t)r * NN * 192;

    int tid = threadIdx.x;
    int mg = tid >> 4;   // 0..7  (8 rows each)
    int ng = tid & 15;   // 0..15 (12 cols each)

    __shared__ float As[16][64];
    __shared__ float Bs[16][192];

    unsigned long long acc[8][6];   // packed f32x2 accumulators
#pragma unroll
    for (int i = 0; i < 8; i++)
#pragma unroll
        for (int j = 0; j < 6; j++) acc[i][j] = 0ULL;

    for (int k0 = 0; k0 < FIN; k0 += 16) {
        // load A tile (64 rows x 16 k), transposed into As[k][m]
        for (int t = tid; t < 256; t += 128) {
            int m = t & 63, kq = t >> 6;
            int row = row0 + m;
            float4 v = make_float4(0.f, 0.f, 0.f, 0.f);
            if (row < NN) v = *(const float4*)&A[(size_t)row * FIN + k0 + kq * 4];
            As[kq * 4 + 0][m] = v.x;
            As[kq * 4 + 1][m] = v.y;
            As[kq * 4 + 2][m] = v.z;
            As[kq * 4 + 3][m] = v.w;
        }
        // load B tile (16 k x 192 cols) with on-the-fly [W0-W2 | W1 | W2] combine
        for (int t = tid; t < 768; t += 128) {
            int row = t / 48;               // k within tile
            int c4 = (t - row * 48) * 4;    // col 0..188
            int kk = k0 + row;
            float4 v;
            if (c4 < 64) {
                float4 v0 = *(const float4*)&Wr[(size_t)kk * 64 + c4];
                float4 v2 = *(const float4*)&Wr[(size_t)(2 * FIN + kk) * 64 + c4];
                v = make_float4(v0.x - v2.x, v0.y - v2.y, v0.z - v2.z, v0.w - v2.w);
            } else if (c4 < 128) {
                v = *(const float4*)&Wr[(size_t)(FIN + kk) * 64 + (c4 - 64)];
            } else {
                v = *(const float4*)&Wr[(size_t)(2 * FIN + kk) * 64 + (c4 - 128)];
            }
            *(float4*)&Bs[row][c4] = v;
        }
        __syncthreads();

#pragma unroll
        for (int k = 0; k < 16; k++) {
            float a[8];
            *(float4*)&a[0] = *(const float4*)&As[k][mg * 8];
            *(float4*)&a[4] = *(const float4*)&As[k][mg * 8 + 4];
            unsigned long long b2[6];
            const ulonglong2* Bd2 = (const ulonglong2*)&Bs[k][ng * 12];
            ulonglong2 t0 = Bd2[0], t1 = Bd2[1], t2 = Bd2[2];
            b2[0] = t0.x; b2[1] = t0.y; b2[2] = t1.x; b2[3] = t1.y; b2[4] = t2.x; b2[5] = t2.y;
#pragma unroll
            for (int i = 0; i < 8; i++) {
                unsigned long long a2;
                asm("mov.b64 %0, {%1, %1};" : "=l"(a2) : "f"(a[i]));
#pragma unroll
                for (int j = 0; j < 6; j++)
                    asm("fma.rn.f32x2 %0, %1, %2, %0;" : "+l"(acc[i][j]) : "l"(a2), "l"(b2[j]));
            }
        }
        __syncthreads();
    }
#pragma unroll
    for (int i = 0; i < 8; i++) {
        int row = row0 + mg * 8 + i;
        if (row < NN) {
            unsigned long long* op = (unsigned long long*)(O + (size_t)row * 192 + ng * 12);
#pragma unroll
            for (int j = 0; j < 6; j++) op[j] = acc[i][j];
        }
    }
}

// ---------------- CSR SpMM, warp per destination row ----------------
// MODE 0: w   = yQ + 2*lhat(yS)                 (no bias/relu)
// MODE 1: h1  = relu(yP + lhat(w) + b1)   -> g_h
// MODE 2: h2  = relu(yP + lhat(w) + b2)   -> g_stack (strided)
template <int MODE>
__global__ void __launch_bounds__(256) k_spmm(const float* __restrict__ bias) {
    int r = blockIdx.y;
    int node = blockIdx.x * 8 + (threadIdx.x >> 5);
    if (node >= NN) return;
    int l = threadIdx.x & 31, f0 = l * 2;

    const int2* ed = g_edata + (size_t)r * EE;
    const int* rp = g_rowptr + r * (NN + 1);

    const float* vin;
    int vs;
    if (MODE == 0) { vin = g_y + (size_t)r * NN * 192 + 128; vs = 192; }
    else           { vin = g_w + (size_t)r * NN * 64;        vs = 64; }
    const float* add;
    if (MODE == 0) add = g_y + (size_t)r * NN * 192 + 64;
    else           add = g_y + (size_t)r * NN * 192;
    float* op;
    int os;
    if (MODE == 0)      { op = g_w + (size_t)r * NN * 64;  os = 64; }
    else if (MODE == 1) { op = g_h + (size_t)r * NN * 64;  os = 64; }
    else                { op = g_stack + r * 64;           os = RR * 64; }

    float ax = 0.f, ay = 0.f;
    int s0 = rp[node], s1 = rp[node + 1];
    int j = s0;
    for (; j + 3 < s1; j += 4) {
        int2 e0 = __ldg(&ed[j]);
        int2 e1 = __ldg(&ed[j + 1]);
        int2 e2 = __ldg(&ed[j + 2]);
        int2 e3 = __ldg(&ed[j + 3]);
        float2 v0 = *(const float2*)&vin[(size_t)e0.x * vs + f0];
        float2 v1 = *(const float2*)&vin[(size_t)e1.x * vs + f0];
        float2 v2 = *(const float2*)&vin[(size_t)e2.x * vs + f0];
        float2 v3 = *(const float2*)&vin[(size_t)e3.x * vs + f0];
        float n0 = __int_as_float(e0.y), n1 = __int_as_float(e1.y);
        float n2 = __int_as_float(e2.y), n3 = __int_as_float(e3.y);
        ax = fmaf(n0, v0.x, ax); ay = fmaf(n0, v0.y, ay);
        ax = fmaf(n1, v1.x, ax); ay = fmaf(n1, v1.y, ay);
        ax = fmaf(n2, v2.x, ax); ay = fmaf(n2, v2.y, ay);
        ax = fmaf(n3, v3.x, ax); ay = fmaf(n3, v3.y, ay);
    }
    for (; j < s1; j++) {
        int2 e0 = __ldg(&ed[j]);
        float n0 = __int_as_float(e0.y);
        float2 v0 = *(const float2*)&vin[(size_t)e0.x * vs + f0];
        ax = fmaf(n0, v0.x, ax); ay = fmaf(n0, v0.y, ay);
    }

    float2 ad = *(const float2*)&add[(size_t)node * 192 + f0];
    float alpha = (MODE == 0) ? 2.0f : 1.0f;
    float ox = ad.x + alpha * ax;
    float oy = ad.y + alpha * ay;
    if (MODE != 0) {
        ox += bias[r * 64 + f0];
        oy += bias[r * 64 + f0 + 1];
        ox = fmaxf(ox, 0.f);
        oy = fmaxf(oy, 0.f);
    }
    *(float2*)&op[(size_t)node * os + f0] = make_float2(ox, oy);
}

// ---------------- fused gate / softmax / proj / cls / aux, warp per node ----------------
__device__ __forceinline__ float wsum(float v) {
#pragma unroll
    for (int o = 16; o; o >>= 1) v += __shfl_xor_sync(0xffffffffu, v, o);
    return v;
}

__global__ void __launch_bounds__(256) k_final(
    const float* __restrict__ gw1, const float* __restrict__ gb1,
    const float* __restrict__ gw2, const float* __restrict__ gb2,
    const float* __restrict__ pw,  const float* __restrict__ pb,
    const float* __restrict__ cw1, const float* __restrict__ cb1,
    const float* __restrict__ cw2, const float* __restrict__ cb2,
    const float* __restrict__ aw,  const float* __restrict__ ab,
    float* __restrict__ out)
{
    __shared__ float s_s[8][RR * 64];
    __shared__ float s_t[8][64];
    int w = threadIdx.x >> 5, l = threadIdx.x & 31;
    int node = blockIdx.x * 8 + w;
    if (node >= NN) return;
    int f0 = l * 2;

    const float* srow = g_stack + (size_t)node * (RR * 64);
    float2 sv[RR];
#pragma unroll
    for (int r = 0; r < RR; r++) {
        sv[r] = *(const float2*)&srow[r * 64 + f0];
        s_s[w][r * 64 + f0] = sv[r].x;
        s_s[w][r * 64 + f0 + 1] = sv[r].y;
    }
    __syncwarp();

    // aux logits
#pragma unroll
    for (int r = 0; r < RR; r++) {
        float p = sv[r].x * __ldg(&aw[r * 64 + f0]) + sv[r].y * __ldg(&aw[r * 64 + f0 + 1]);
        p = wsum(p);
        if (l == 0) out[NN + (size_t)node * RR + r] = p + __ldg(&ab[r]);
    }

    // gate MLP per relation
    float g[RR];
    float b0 = __ldg(&gb1[f0]), b1 = __ldg(&gb1[f0 + 1]);
    float w20 = __ldg(&gw2[f0]), w21 = __ldg(&gw2[f0 + 1]);
    float gb2v = __ldg(&gb2[0]);
#pragma unroll
    for (int r = 0; r < RR; r++) {
        float t0 = b0, t1 = b1;
        const float* sr = &s_s[w][r * 64];
#pragma unroll 8
        for (int i = 0; i < 64; i++) {
            float si = sr[i];
            float2 wv = *(const float2*)&gw1[i * 64 + f0];
            t0 = fmaf(si, wv.x, t0);
            t1 = fmaf(si, wv.y, t1);
        }
        float gp = fmaxf(t0, 0.f) * w20 + fmaxf(t1, 0.f) * w21;
        g[r] = wsum(gp) + gb2v;
    }

    // softmax over relations, fused embedding
    float m = g[0];
#pragma unroll
    for (int r = 1; r < RR; r++) m = fmaxf(m, g[r]);
    float es = 0.f, e[RR];
#pragma unroll
    for (int r = 0; r < RR; r++) { e[r] = expf(g[r] - m); es += e[r]; }
    float inv = 1.0f / es;
    float fx = 0.f, fy = 0.f;
#pragma unroll
    for (int r = 0; r < RR; r++) {
        float a = e[r] * inv;
        fx = fmaf(a, sv[r].x, fx);
        fy = fmaf(a, sv[r].y, fy);
    }
    s_t[w][f0] = fx; s_t[w][f0 + 1] = fy;
    __syncwarp();

    // proj
    float t0 = __ldg(&pb[f0]), t1 = __ldg(&pb[f0 + 1]);
#pragma unroll 8
    for (int i = 0; i < 64; i++) {
        float fi = s_t[w][i];
        float2 wv = *(const float2*)&pw[i * 64 + f0];
        t0 = fmaf(fi, wv.x, t0);
        t1 = fmaf(fi, wv.y, t1);
    }
    float hp0 = fmaxf(t0, 0.f), hp1 = fmaxf(t1, 0.f);
    __syncwarp();
    s_t[w][f0] = hp0; s_t[w][f0 + 1] = hp1;
    __syncwarp();

    // cls layer 1 + output dot
    t0 = __ldg(&cb1[f0]); t1 = __ldg(&cb1[f0 + 1]);
#pragma unroll 8
    for (int i = 0; i < 64; i++) {
        float hi = s_t[w][i];
        float2 wv = *(const float2*)&cw1[i * 64 + f0];
        t0 = fmaf(hi, wv.x, t0);
        t1 = fmaf(hi, wv.y, t1);
    }
    float c0 = fmaxf(t0, 0.f), c1 = fmaxf(t1, 0.f);
    float lp = c0 * __ldg(&cw2[f0]) + c1 * __ldg(&cw2[f0 + 1]);
    lp = wsum(lp);
    if (l == 0) out[node] = lp + __ldg(&cb2[0]);
}

// ---------------- launch ----------------
extern "C" void kernel_launch(void* const* d_in, const int* in_sizes, int n_in,
                              void* d_out, int out_size) {
    const float* x       = (const float*)d_in[0];
    const int*   ei      = (const int*)d_in[1];
    const float* cheb1_w = (const float*)d_in[2];
    const float* cheb1_b = (const float*)d_in[3];
    const float* cheb2_w = (const float*)d_in[4];
    const float* cheb2_b = (const float*)d_in[5];
    const float* gate_w1 = (const float*)d_in[6];
    const float* gate_b1 = (const float*)d_in[7];
    const float* gate_w2 = (const float*)d_in[8];
    const float* gate_b2 = (const float*)d_in[9];
    const float* proj_w  = (const float*)d_in[10];
    const float* proj_b  = (const float*)d_in[11];
    const float* cls_w1  = (const float*)d_in[12];
    const float* cls_b1  = (const float*)d_in[13];
    const float* cls_w2  = (const float*)d_in[14];
    const float* cls_b2  = (const float*)d_in[15];
    const float* aux_w   = (const float*)d_in[16];
    const float* aux_b   = (const float*)d_in[17];
    float* out = (float*)d_out;

    // CSR build (dis fused into scan)
    k_zero<<<(RR * NN + 255) / 256, 256>>>();
    k_count<<<(RR * EE + 255) / 256, 256>>>(ei);
    k_scan<<<RR, 1024>>>();
    k_scatter<<<(RR * EE + 255) / 256, 256>>>(ei);

    dim3 ggrid1((NN + 63) / 64, RR);
    dim3 sgrid((NN + 7) / 8, RR);

    // layer 1
    k_gemm<DIN, true><<<ggrid1, 128>>>(x, cheb1_w);
    k_spmm<0><<<sgrid, 256>>>(nullptr);
    k_spmm<1><<<sgrid, 256>>>(cheb1_b);
    // layer 2
    k_gemm<HH, false><<<ggrid1, 128>>>(nullptr, cheb2_w);
    k_spmm<0><<<sgrid, 256>>>(nullptr);
    k_spmm<2><<<sgrid, 256>>>(cheb2_b);
    // fusion + heads
    k_final<<<(NN + 7) / 8, 256>>>(gate_w1, gate_b1, gate_w2, gate_b2,
                                   proj_w, proj_b, cls_w1, cls_b1, cls_w2, cls_b2,
                                   aux_w, aux_b, out);
}

// round 5
// speedup vs baseline: 1.1122x; 1.1122x over previous
#include <cuda_runtime.h>
#include <cuda_bf16.h>
#include <math.h>

#define NN 100000
#define EE 1600000
#define RR 6
#define DIN 128
#define HH 64

// ---------------- scratch (static device memory; no allocation at runtime) ----------------
static __device__ int   g_deg[RR * NN];
static __device__ float g_dis[RR * NN];
static __device__ int   g_rowptr[RR * (NN + 1)];
static __device__ int   g_next[RR * NN];
static __device__ int2  g_edata[(size_t)RR * EE];
static __device__ float g_wc1[RR * DIN * 192];
static __device__ float g_wc2[RR * HH * 192];
static __device__ float g_y[(size_t)RR * NN * 192];     // P|Q|S projections per relation
static __device__ float g_w[(size_t)RR * NN * HH];      // intermediate w = Q + 2*lhat(S)
static __device__ float g_h[(size_t)RR * NN * HH];      // layer-1 output h1
static __device__ float g_stack[(size_t)NN * RR * HH];  // final per-relation embeddings

// ---------------- weight prep: Wcomb = [W0-W2 | W1 | W2] ----------------
__global__ void k_prep(const float* __restrict__ w1, const float* __restrict__ w2) {
    int id = blockIdx.x * blockDim.x + threadIdx.x;
    if (id < RR * DIN * 192) {
        int o = id % 192, c = o >> 6, oo = o & 63;
        int i = (id / 192) % DIN;
        int r = id / (192 * DIN);
        size_t base = ((size_t)(r * 3) * DIN + i) * 64;
        float v;
        if (c == 0)      v = w1[base + oo] - w1[base + 2 * DIN * 64 + oo];
        else if (c == 1) v = w1[base + DIN * 64 + oo];
        else             v = w1[base + 2 * DIN * 64 + oo];
        g_wc1[id] = v;
    } else {
        int id2 = id - RR * DIN * 192;
        if (id2 < RR * HH * 192) {
            int o = id2 % 192, c = o >> 6, oo = o & 63;
            int i = (id2 / 192) % HH;
            int r = id2 / (192 * HH);
            size_t base = ((size_t)(r * 3) * HH + i) * 64;
            float v;
            if (c == 0)      v = w2[base + oo] - w2[base + 2 * HH * 64 + oo];
            else if (c == 1) v = w2[base + HH * 64 + oo];
            else             v = w2[base + 2 * HH * 64 + oo];
            g_wc2[id2] = v;
        }
    }
}

// ---------------- CSR build ----------------
__global__ void k_zero() {
    int id = blockIdx.x * blockDim.x + threadIdx.x;
    if (id < RR * NN) { g_deg[id] = 0; g_next[id] = 0; }
}

__global__ void k_count(const int* __restrict__ ei) {
    int id = blockIdx.x * blockDim.x + threadIdx.x;
    if (id >= RR * EE) return;
    int r = id / EE, e = id - r * EE;
    int src = ei[(size_t)(r * 2) * EE + e];
    int dst = ei[(size_t)(r * 2 + 1) * EE + e];
    atomicAdd(&g_deg[r * NN + src], 1);
    atomicAdd(&g_next[r * NN + dst], 1);   // g_next holds in-degree counts for now
}

// one block per relation: exclusive scan of in-degree counts -> rowptr, init g_next = rowptr.
// Also computes g_dis from out-degree (fused former k_dis).
__global__ void k_scan() {
    __shared__ int ssum[1024];
    const int CH = (NN + 1023) / 1024;   // 98
    int r = blockIdx.x;
    int t = threadIdx.x;
    int base = r * NN;
    int st = t * CH;
    int local = 0;
    for (int i = 0; i < CH; i++) {
        int idx = st + i;
        if (idx < NN) local += g_next[base + idx];
    }
    ssum[t] = local;
    __syncthreads();
    for (int off = 1; off < 1024; off <<= 1) {
        int v = (t >= off) ? ssum[t - off] : 0;
        __syncthreads();
        ssum[t] += v;
        __syncthreads();
    }
    int run = ssum[t] - local;  // exclusive prefix
    for (int i = 0; i < CH; i++) {
        int idx = st + i;
        if (idx < NN) {
            int c = g_next[base + idx];
            g_rowptr[r * (NN + 1) + idx] = run;
            g_next[base + idx] = run;
            run += c;
            int d = g_deg[base + idx];
            g_dis[base + idx] = (d > 0) ? rsqrtf((float)d) : 0.0f;
        }
    }
    if (t == 1023) g_rowptr[r * (NN + 1) + NN] = ssum[1023];
}

__global__ void k_scatter(const int* __restrict__ ei) {
    int id = blockIdx.x * blockDim.x + threadIdx.x;
    if (id >= RR * EE) return;
    int r = id / EE, e = id - r * EE;
    int src = ei[(size_t)(r * 2) * EE + e];
    int dst = ei[(size_t)(r * 2 + 1) * EE + e];
    int pos = atomicAdd(&g_next[r * NN + dst], 1);
    float nv = -g_dis[r * NN + src] * g_dis[r * NN + dst];
    g_edata[(size_t)r * EE + pos] = make_int2(src, __float_as_int(nv));
}

// ---------------- fused GEMM: [N,FIN] @ Wcomb[FIN,192] -> g_y ----------------
template <int FIN, bool XIN>
__global__ void __launch_bounds__(128) k_gemm(const float* __restrict__ xin) {
    const int r = blockIdx.y;
    const int row0 = blockIdx.x * 64;
    const float* A = XIN ? xin : (g_h + (size_t)r * NN * HH);
    const float* W = (FIN == 128) ? (g_wc1 + (size_t)r * FIN * 192)
                                  : (g_wc2 + (size_t)r * FIN * 192);
    float* O = g_y + (size_t)r * NN * 192;

    int tid = threadIdx.x;
    int mg = tid >> 4;   // 0..7  (8 rows each)
    int ng = tid & 15;   // 0..15 (12 cols each)

    __shared__ float As[16][64];
    __shared__ float Bs[16][192];

    float acc[8][12];
#pragma unroll
    for (int i = 0; i < 8; i++)
#pragma unroll
        for (int j = 0; j < 12; j++) acc[i][j] = 0.0f;

    for (int k0 = 0; k0 < FIN; k0 += 16) {
        // load A tile (64 rows x 16 k), transposed into As[k][m]
        for (int t = tid; t < 256; t += 128) {
            int m = t & 63, kq = t >> 6;
            int row = row0 + m;
            float4 v = make_float4(0.f, 0.f, 0.f, 0.f);
            if (row < NN) v = *(const float4*)&A[(size_t)row * FIN + k0 + kq * 4];
            As[kq * 4 + 0][m] = v.x;
            As[kq * 4 + 1][m] = v.y;
            As[kq * 4 + 2][m] = v.z;
            As[kq * 4 + 3][m] = v.w;
        }
        // load B tile (16 k x 192 cols)
        const float4* W4 = (const float4*)(W + (size_t)k0 * 192);
        float4* B4 = (float4*)(&Bs[0][0]);
        for (int t = tid; t < 768; t += 128) B4[t] = W4[t];
        __syncthreads();

#pragma unroll
        for (int k = 0; k < 16; k++) {
            float a[8], b[12];
            *(float4*)&a[0] = *(const float4*)&As[k][mg * 8];
            *(float4*)&a[4] = *(const float4*)&As[k][mg * 8 + 4];
            *(float4*)&b[0] = *(const float4*)&Bs[k][ng * 12];
            *(float4*)&b[4] = *(const float4*)&Bs[k][ng * 12 + 4];
            *(float4*)&b[8] = *(const float4*)&Bs[k][ng * 12 + 8];
#pragma unroll
            for (int i = 0; i < 8; i++)
#pragma unroll
                for (int j = 0; j < 12; j++) acc[i][j] = fmaf(a[i], b[j], acc[i][j]);
        }
        __syncthreads();
    }
#pragma unroll
    for (int i = 0; i < 8; i++) {
        int row = row0 + mg * 8 + i;
        if (row < NN) {
            float* op = O + (size_t)row * 192 + ng * 12;
            *(float4*)&op[0] = *(float4*)&acc[i][0];
            *(float4*)&op[4] = *(float4*)&acc[i][4];
            *(float4*)&op[8] = *(float4*)&acc[i][8];
        }
    }
}

// ---------------- CSR SpMM, half-warp (16 lanes x float4) per destination row ----------------
// MODE 0: w   = yQ + 2*lhat(yS)                 (no bias/relu)
// MODE 1: h1  = relu(yP + lhat(w) + b1)   -> g_h
// MODE 2: h2  = relu(yP + lhat(w) + b2)   -> g_stack (strided)
template <int MODE>
__global__ void __launch_bounds__(256) k_spmm(const float* __restrict__ bias) {
    int r = blockIdx.y;
    int node = blockIdx.x * 16 + (threadIdx.x >> 4);
    if (node >= NN) return;
    int l = threadIdx.x & 15, f0 = l * 4;

    const int2* ed = g_edata + (size_t)r * EE;
    const int* rp = g_rowptr + r * (NN + 1);

    const float* vin;
    int vs;
    if (MODE == 0) { vin = g_y + (size_t)r * NN * 192 + 128; vs = 192; }
    else           { vin = g_w + (size_t)r * NN * 64;        vs = 64; }
    const float* add;
    if (MODE == 0) add = g_y + (size_t)r * NN * 192 + 64;
    else           add = g_y + (size_t)r * NN * 192;
    float* op;
    int os;
    if (MODE == 0)      { op = g_w + (size_t)r * NN * 64;  os = 64; }
    else if (MODE == 1) { op = g_h + (size_t)r * NN * 64;  os = 64; }
    else                { op = g_stack + r * 64;           os = RR * 64; }

    float ax = 0.f, ay = 0.f, az = 0.f, aw = 0.f;
    int s0 = rp[node], s1 = rp[node + 1];
    int j = s0;
    for (; j + 1 < s1; j += 2) {
        int2 e0 = __ldg(&ed[j]);
        int2 e1 = __ldg(&ed[j + 1]);
        float4 v0 = *(const float4*)&vin[(size_t)e0.x * vs + f0];
        float4 v1 = *(const float4*)&vin[(size_t)e1.x * vs + f0];
        float n0 = __int_as_float(e0.y), n1 = __int_as_float(e1.y);
        ax = fmaf(n0, v0.x, ax); ay = fmaf(n0, v0.y, ay);
        az = fmaf(n0, v0.z, az); aw = fmaf(n0, v0.w, aw);
        ax = fmaf(n1, v1.x, ax); ay = fmaf(n1, v1.y, ay);
        az = fmaf(n1, v1.z, az); aw = fmaf(n1, v1.w, aw);
    }
    if (j < s1) {
        int2 e0 = __ldg(&ed[j]);
        float n0 = __int_as_float(e0.y);
        float4 v0 = *(const float4*)&vin[(size_t)e0.x * vs + f0];
        ax = fmaf(n0, v0.x, ax); ay = fmaf(n0, v0.y, ay);
        az = fmaf(n0, v0.z, az); aw = fmaf(n0, v0.w, aw);
    }

    float4 ad = *(const float4*)&add[(size_t)node * 192 + f0];
    float alpha = (MODE == 0) ? 2.0f : 1.0f;
    float ox = ad.x + alpha * ax;
    float oy = ad.y + alpha * ay;
    float oz = ad.z + alpha * az;
    float ow = ad.w + alpha * aw;
    if (MODE != 0) {
        float4 bv = *(const float4*)&bias[r * 64 + f0];
        ox = fmaxf(ox + bv.x, 0.f);
        oy = fmaxf(oy + bv.y, 0.f);
        oz = fmaxf(oz + bv.z, 0.f);
        ow = fmaxf(ow + bv.w, 0.f);
    }
    *(float4*)&op[(size_t)node * os + f0] = make_float4(ox, oy, oz, ow);
}

// ---------------- fused gate / softmax / proj / cls / aux, warp per node ----------------
__device__ __forceinline__ float wsum(float v) {
#pragma unroll
    for (int o = 16; o; o >>= 1) v += __shfl_xor_sync(0xffffffffu, v, o);
    return v;
}

__global__ void __launch_bounds__(256) k_final(
    const float* __restrict__ gw1, const float* __restrict__ gb1,
    const float* __restrict__ gw2, const float* __restrict__ gb2,
    const float* __restrict__ pw,  const float* __restrict__ pb,
    const float* __restrict__ cw1, const float* __restrict__ cb1,
    const float* __restrict__ cw2, const float* __restrict__ cb2,
    const float* __restrict__ aw,  const float* __restrict__ ab,
    float* __restrict__ out)
{
    __shared__ float s_s[8][RR * 64];
    __shared__ float s_t[8][64];
    int w = threadIdx.x >> 5, l = threadIdx.x & 31;
    int node = blockIdx.x * 8 + w;
    if (node >= NN) return;
    int f0 = l * 2;

    const float* srow = g_stack + (size_t)node * (RR * 64);
    float2 sv[RR];
#pragma unroll
    for (int r = 0; r < RR; r++) {
        sv[r] = *(const float2*)&srow[r * 64 + f0];
        s_s[w][r * 64 + f0] = sv[r].x;
        s_s[w][r * 64 + f0 + 1] = sv[r].y;
    }
    __syncwarp();

    // aux logits
#pragma unroll
    for (int r = 0; r < RR; r++) {
        float p = sv[r].x * __ldg(&aw[r * 64 + f0]) + sv[r].y * __ldg(&aw[r * 64 + f0 + 1]);
        p = wsum(p);
        if (l == 0) out[NN + (size_t)node * RR + r] = p + __ldg(&ab[r]);
    }

    // gate MLP per relation
    float g[RR];
    float b0 = __ldg(&gb1[f0]), b1 = __ldg(&gb1[f0 + 1]);
    float w20 = __ldg(&gw2[f0]), w21 = __ldg(&gw2[f0 + 1]);
    float gb2v = __ldg(&gb2[0]);
#pragma unroll
    for (int r = 0; r < RR; r++) {
        float t0 = b0, t1 = b1;
        const float* sr = &s_s[w][r * 64];
#pragma unroll 8
        for (int i = 0; i < 64; i++) {
            float si = sr[i];
            float2 wv = *(const float2*)&gw1[i * 64 + f0];
            t0 = fmaf(si, wv.x, t0);
            t1 = fmaf(si, wv.y, t1);
        }
        float gp = fmaxf(t0, 0.f) * w20 + fmaxf(t1, 0.f) * w21;
        g[r] = wsum(gp) + gb2v;
    }

    // softmax over relations, fused embedding
    float m = g[0];
#pragma unroll
    for (int r = 1; r < RR; r++) m = fmaxf(m, g[r]);
    float es = 0.f, e[RR];
#pragma unroll
    for (int r = 0; r < RR; r++) { e[r] = expf(g[r] - m); es += e[r]; }
    float inv = 1.0f / es;
    float fx = 0.f, fy = 0.f;
#pragma unroll
    for (int r = 0; r < RR; r++) {
        float a = e[r] * inv;
        fx = fmaf(a, sv[r].x, fx);
        fy = fmaf(a, sv[r].y, fy);
    }
    s_t[w][f0] = fx; s_t[w][f0 + 1] = fy;
    __syncwarp();

    // proj
    float t0 = __ldg(&pb[f0]), t1 = __ldg(&pb[f0 + 1]);
#pragma unroll 8
    for (int i = 0; i < 64; i++) {
        float fi = s_t[w][i];
        float2 wv = *(const float2*)&pw[i * 64 + f0];
        t0 = fmaf(fi, wv.x, t0);
        t1 = fmaf(fi, wv.y, t1);
    }
    float hp0 = fmaxf(t0, 0.f), hp1 = fmaxf(t1, 0.f);
    __syncwarp();
    s_t[w][f0] = hp0; s_t[w][f0 + 1] = hp1;
    __syncwarp();

    // cls layer 1 + output dot
    t0 = __ldg(&cb1[f0]); t1 = __ldg(&cb1[f0 + 1]);
#pragma unroll 8
    for (int i = 0; i < 64; i++) {
        float hi = s_t[w][i];
        float2 wv = *(const float2*)&cw1[i * 64 + f0];
        t0 = fmaf(hi, wv.x, t0);
        t1 = fmaf(hi, wv.y, t1);
    }
    float c0 = fmaxf(t0, 0.f), c1 = fmaxf(t1, 0.f);
    float lp = c0 * __ldg(&cw2[f0]) + c1 * __ldg(&cw2[f0 + 1]);
    lp = wsum(lp);
    if (l == 0) out[node] = lp + __ldg(&cb2[0]);
}

// ---------------- launch ----------------
extern "C" void kernel_launch(void* const* d_in, const int* in_sizes, int n_in,
                              void* d_out, int out_size) {
    const float* x       = (const float*)d_in[0];
    const int*   ei      = (const int*)d_in[1];
    const float* cheb1_w = (const float*)d_in[2];
    const float* cheb1_b = (const float*)d_in[3];
    const float* cheb2_w = (const float*)d_in[4];
    const float* cheb2_b = (const float*)d_in[5];
    const float* gate_w1 = (const float*)d_in[6];
    const float* gate_b1 = (const float*)d_in[7];
    const float* gate_w2 = (const float*)d_in[8];
    const float* gate_b2 = (const float*)d_in[9];
    const float* proj_w  = (const float*)d_in[10];
    const float* proj_b  = (const float*)d_in[11];
    const float* cls_w1  = (const float*)d_in[12];
    const float* cls_b1  = (const float*)d_in[13];
    const float* cls_w2  = (const float*)d_in[14];
    const float* cls_b2  = (const float*)d_in[15];
    const float* aux_w   = (const float*)d_in[16];
    const float* aux_b   = (const float*)d_in[17];
    float* out = (float*)d_out;

    // weight prep + CSR build
    k_prep<<<(RR * DIN * 192 + RR * HH * 192 + 255) / 256, 256>>>(cheb1_w, cheb2_w);
    k_zero<<<(RR * NN + 255) / 256, 256>>>();
    k_count<<<(RR * EE + 255) / 256, 256>>>(ei);
    k_scan<<<RR, 1024>>>();
    k_scatter<<<(RR * EE + 255) / 256, 256>>>(ei);

    dim3 ggrid1((NN + 63) / 64, RR);
    dim3 sgrid((NN + 15) / 16, RR);

    // layer 1
    k_gemm<DIN, true><<<ggrid1, 128>>>(x);
    k_spmm<0><<<sgrid, 256>>>(nullptr);
    k_spmm<1><<<sgrid, 256>>>(cheb1_b);
    // layer 2
    k_gemm<HH, false><<<ggrid1, 128>>>(nullptr);
    k_spmm<0><<<sgrid, 256>>>(nullptr);
    k_spmm<2><<<sgrid, 256>>>(cheb2_b);
    // fusion + heads
    k_final<<<(NN + 7) / 8, 256>>>(gate_w1, gate_b1, gate_w2, gate_b2,
                                   proj_w, proj_b, cls_w1, cls_b1, cls_w2, cls_b2,
                                   aux_w, aux_b, out);
}

// round 7
// speedup vs baseline: 1.1689x; 1.0511x over previous
#include <cuda_runtime.h>
#include <cuda_bf16.h>
#include <math.h>

#define NN 100000
#define EE 1600000
#define RR 6
#define DIN 128
#define HH 64
#define NB 98   // ceil(NN/1024)

// ---------------- scratch (static device memory; no allocation at runtime) ----------------
static __device__ int   g_deg[RR * NN];
static __device__ float g_dis[RR * NN];
static __device__ int   g_rowptr[RR * (NN + 1)];
static __device__ int   g_next[RR * NN];
static __device__ int   g_psum[RR * NB];
static __device__ int2  g_edata[(size_t)RR * EE];
static __device__ float g_wc1[RR * DIN * 192];
static __device__ float g_wc2[RR * HH * 192];
static __device__ float g_y[(size_t)RR * NN * 192];     // P|Q|S projections per relation
static __device__ float g_w[(size_t)RR * NN * HH];      // intermediate w = Q + 2*lhat(S)
static __device__ float g_h[(size_t)RR * NN * HH];      // layer-1 output h1
static __device__ float g_stack[(size_t)NN * RR * HH];  // final per-relation embeddings

// ---------------- weight prep: Wcomb = [W0-W2 | W1 | W2] ----------------
__global__ void k_prep(const float* __restrict__ w1, const float* __restrict__ w2) {
    int id = blockIdx.x * blockDim.x + threadIdx.x;
    if (id < RR * DIN * 192) {
        int o = id % 192, c = o >> 6, oo = o & 63;
        int i = (id / 192) % DIN;
        int r = id / (192 * DIN);
        size_t base = ((size_t)(r * 3) * DIN + i) * 64;
        float v;
        if (c == 0)      v = w1[base + oo] - w1[base + 2 * DIN * 64 + oo];
        else if (c == 1) v = w1[base + DIN * 64 + oo];
        else             v = w1[base + 2 * DIN * 64 + oo];
        g_wc1[id] = v;
    } else {
        int id2 = id - RR * DIN * 192;
        if (id2 < RR * HH * 192) {
            int o = id2 % 192, c = o >> 6, oo = o & 63;
            int i = (id2 / 192) % HH;
            int r = id2 / (192 * HH);
            size_t base = ((size_t)(r * 3) * HH + i) * 64;
            float v;
            if (c == 0)      v = w2[base + oo] - w2[base + 2 * HH * 64 + oo];
            else if (c == 1) v = w2[base + HH * 64 + oo];
            else             v = w2[base + 2 * HH * 64 + oo];
            g_wc2[id2] = v;
        }
    }
}

// ---------------- CSR build ----------------
__global__ void k_zero() {
    int id = blockIdx.x * blockDim.x + threadIdx.x;
    if (id < RR * NN) { g_deg[id] = 0; g_next[id] = 0; }
}

__global__ void k_count(const int* __restrict__ ei) {
    int id = blockIdx.x * blockDim.x + threadIdx.x;
    if (id >= RR * EE) return;
    int r = id / EE, e = id - r * EE;
    int src = ei[(size_t)(r * 2) * EE + e];
    int dst = ei[(size_t)(r * 2 + 1) * EE + e];
    atomicAdd(&g_deg[r * NN + src], 1);
    atomicAdd(&g_next[r * NN + dst], 1);   // g_next holds in-degree counts for now
}

// ---- phase A: per-1024-chunk partial sums of in-degree counts; fused g_dis compute ----
__global__ void __launch_bounds__(1024) k_part() {
    int b = blockIdx.x;                 // 0 .. RR*NB-1
    int r = b / NB, cb = b - r * NB;
    int idx = cb * 1024 + threadIdx.x;
    int v = 0;
    if (idx < NN) {
        v = g_next[r * NN + idx];
        int d = g_deg[r * NN + idx];
        g_dis[r * NN + idx] = (d > 0) ? rsqrtf((float)d) : 0.0f;
    }
    __shared__ int swp[32];
    int l = threadIdx.x & 31, w = threadIdx.x >> 5;
    int s = v;
#pragma unroll
    for (int o = 16; o; o >>= 1) s += __shfl_xor_sync(0xffffffffu, s, o);
    if (l == 0) swp[w] = s;
    __syncthreads();
    if (w == 0) {
        int t = (l < 32) ? swp[l] : 0;
#pragma unroll
        for (int o = 16; o; o >>= 1) t += __shfl_xor_sync(0xffffffffu, t, o);
        if (l == 0) g_psum[b] = t;
    }
}

// ---- phase B: exclusive scan of NB partials per relation (RR blocks of 128) ----
__global__ void __launch_bounds__(128) k_mid() {
    __shared__ int sv[128];
    int r = blockIdx.x, t = threadIdx.x;
    int v = (t < NB) ? g_psum[r * NB + t] : 0;
    sv[t] = v;
    __syncthreads();
#pragma unroll
    for (int off = 1; off < 128; off <<= 1) {
        int u = (t >= off) ? sv[t - off] : 0;
        __syncthreads();
        sv[t] += u;
        __syncthreads();
    }
    if (t < NB) g_psum[r * NB + t] = sv[t] - v;   // exclusive
    if (t == 127) g_rowptr[r * (NN + 1) + NN] = sv[127];
}

// ---- phase C: block-local exclusive scan + offset -> rowptr, g_next ----
__global__ void __launch_bounds__(1024) k_rowptr() {
    __shared__ int sv[1024];
    int b = blockIdx.x;
    int r = b / NB, cb = b - r * NB;
    int idx = cb * 1024 + threadIdx.x;
    int t = threadIdx.x;
    int c = (idx < NN) ? g_next[r * NN + idx] : 0;
    sv[t] = c;
    __syncthreads();
#pragma unroll
    for (int off = 1; off < 1024; off <<= 1) {
        int u = (t >= off) ? sv[t - off] : 0;
        __syncthreads();
        sv[t] += u;
        __syncthreads();
    }
    if (idx < NN) {
        int run = g_psum[b] + sv[t] - c;    // exclusive within relation
        g_rowptr[r * (NN + 1) + idx] = run;
        g_next[r * NN + idx] = run;
    }
}

__global__ void k_scatter(const int* __restrict__ ei) {
    int id = blockIdx.x * blockDim.x + threadIdx.x;
    if (id >= RR * EE) return;
    int r = id / EE, e = id - r * EE;
    int src = ei[(size_t)(r * 2) * EE + e];
    int dst = ei[(size_t)(r * 2 + 1) * EE + e];
    int pos = atomicAdd(&g_next[r * NN + dst], 1);
    float nv = -g_dis[r * NN + src] * g_dis[r * NN + dst];
    g_edata[(size_t)r * EE + pos] = make_int2(src, __float_as_int(nv));
}

// ---------------- fused GEMM: [N,FIN] @ Wcomb[FIN,192] -> g_y ----------------
template <int FIN, bool XIN>
__global__ void __launch_bounds__(128) k_gemm(const float* __restrict__ xin) {
    const int r = blockIdx.y;
    const int row0 = blockIdx.x * 64;
    const float* A = XIN ? xin : (g_h + (size_t)r * NN * HH);
    const float* W = (FIN == 128) ? (g_wc1 + (size_t)r * FIN * 192)
                                  : (g_wc2 + (size_t)r * FIN * 192);
    float* O = g_y + (size_t)r * NN * 192;

    int tid = threadIdx.x;
    int mg = tid >> 4;   // 0..7  (8 rows each)
    int ng = tid & 15;   // 0..15 (12 cols each)

    __shared__ float As[16][64];
    __shared__ float Bs[16][192];

    float acc[8][12];
#pragma unroll
    for (int i = 0; i < 8; i++)
#pragma unroll
        for (int j = 0; j < 12; j++) acc[i][j] = 0.0f;

    for (int k0 = 0; k0 < FIN; k0 += 16) {
        // load A tile (64 rows x 16 k), transposed into As[k][m]
        for (int t = tid; t < 256; t += 128) {
            int m = t & 63, kq = t >> 6;
            int row = row0 + m;
            float4 v = make_float4(0.f, 0.f, 0.f, 0.f);
            if (row < NN) v = *(const float4*)&A[(size_t)row * FIN + k0 + kq * 4];
            As[kq * 4 + 0][m] = v.x;
            As[kq * 4 + 1][m] = v.y;
            As[kq * 4 + 2][m] = v.z;
            As[kq * 4 + 3][m] = v.w;
        }
        // load B tile (16 k x 192 cols)
        const float4* W4 = (const float4*)(W + (size_t)k0 * 192);
        float4* B4 = (float4*)(&Bs[0][0]);
        for (int t = tid; t < 768; t += 128) B4[t] = W4[t];
        __syncthreads();

#pragma unroll
        for (int k = 0; k < 16; k++) {
            float a[8], b[12];
            *(float4*)&a[0] = *(const float4*)&As[k][mg * 8];
            *(float4*)&a[4] = *(const float4*)&As[k][mg * 8 + 4];
            *(float4*)&b[0] = *(const float4*)&Bs[k][ng * 12];
            *(float4*)&b[4] = *(const float4*)&Bs[k][ng * 12 + 4];
            *(float4*)&b[8] = *(const float4*)&Bs[k][ng * 12 + 8];
#pragma unroll
            for (int i = 0; i < 8; i++)
#pragma unroll
                for (int j = 0; j < 12; j++) acc[i][j] = fmaf(a[i], b[j], acc[i][j]);
        }
        __syncthreads();
    }
#pragma unroll
    for (int i = 0; i < 8; i++) {
        int row = row0 + mg * 8 + i;
        if (row < NN) {
            float* op = O + (size_t)row * 192 + ng * 12;
            *(float4*)&op[0] = *(float4*)&acc[i][0];
            *(float4*)&op[4] = *(float4*)&acc[i][4];
            *(float4*)&op[8] = *(float4*)&acc[i][8];
        }
    }
}

// ---------------- CSR SpMM, warp per destination row (float2 lanes) ----------------
// MODE 0: w   = yQ + 2*lhat(yS)                 (no bias/relu)
// MODE 1: h1  = relu(yP + lhat(w) + b1)   -> g_h
// MODE 2: h2  = relu(yP + lhat(w) + b2)   -> g_stack (strided)
template <int MODE>
__global__ void __launch_bounds__(256) k_spmm(const float* __restrict__ bias) {
    int r = blockIdx.y;
    int node = blockIdx.x * 8 + (threadIdx.x >> 5);
    if (node >= NN) return;
    int l = threadIdx.x & 31, f0 = l * 2;

    const int2* ed = g_edata + (size_t)r * EE;
    const int* rp = g_rowptr + r * (NN + 1);

    const float* vin;
    int vs;
    if (MODE == 0) { vin = g_y + (size_t)r * NN * 192 + 128; vs = 192; }
    else           { vin = g_w + (size_t)r * NN * 64;        vs = 64; }
    const float* add;
    if (MODE == 0) add = g_y + (size_t)r * NN * 192 + 64;
    else           add = g_y + (size_t)r * NN * 192;
    float* op;
    int os;
    if (MODE == 0)      { op = g_w + (size_t)r * NN * 64;  os = 64; }
    else if (MODE == 1) { op = g_h + (size_t)r * NN * 64;  os = 64; }
    else                { op = g_stack + r * 64;           os = RR * 64; }

    float ax = 0.f, ay = 0.f;
    int s0 = rp[node], s1 = rp[node + 1];
    int j = s0;
    for (; j + 1 < s1; j += 2) {
        int2 e0 = __ldg(&ed[j]);
        int2 e1 = __ldg(&ed[j + 1]);
        float n0 = __int_as_float(e0.y);
        float n1 = __int_as_float(e1.y);
        float2 v0 = *(const float2*)&vin[(size_t)e0.x * vs + f0];
        float2 v1 = *(const float2*)&vin[(size_t)e1.x * vs + f0];
        ax = fmaf(n0, v0.x, ax); ay = fmaf(n0, v0.y, ay);
        ax = fmaf(n1, v1.x, ax); ay = fmaf(n1, v1.y, ay);
    }
    if (j < s1) {
        int2 e0 = __ldg(&ed[j]);
        float n0 = __int_as_float(e0.y);
        float2 v0 = *(const float2*)&vin[(size_t)e0.x * vs + f0];
        ax = fmaf(n0, v0.x, ax); ay = fmaf(n0, v0.y, ay);
    }

    float2 ad = *(const float2*)&add[(size_t)node * 192 + f0];
    float alpha = (MODE == 0) ? 2.0f : 1.0f;
    float ox = ad.x + alpha * ax;
    float oy = ad.y + alpha * ay;
    if (MODE != 0) {
        ox += bias[r * 64 + f0];
        oy += bias[r * 64 + f0 + 1];
        ox = fmaxf(ox, 0.f);
        oy = fmaxf(oy, 0.f);
    }
    *(float2*)&op[(size_t)node * os + f0] = make_float2(ox, oy);
}

// ---------------- fused gate / softmax / proj / cls / aux, warp per node ----------------
__device__ __forceinline__ float wsum(float v) {
#pragma unroll
    for (int o = 16; o; o >>= 1) v += __shfl_xor_sync(0xffffffffu, v, o);
    return v;
}

__global__ void __launch_bounds__(256) k_final(
    const float* __restrict__ gw1, const float* __restrict__ gb1,
    const float* __restrict__ gw2, const float* __restrict__ gb2,
    const float* __restrict__ pw,  const float* __restrict__ pb,
    const float* __restrict__ cw1, const float* __restrict__ cb1,
    const float* __restrict__ cw2, const float* __restrict__ cb2,
    const float* __restrict__ aw,  const float* __restrict__ ab,
    float* __restrict__ out)
{
    __shared__ float s_s[8][RR * 64];
    __shared__ float s_t[8][64];
    int w = threadIdx.x >> 5, l = threadIdx.x & 31;
    int node = blockIdx.x * 8 + w;
    if (node >= NN) return;
    int f0 = l * 2;

    const float* srow = g_stack + (size_t)node * (RR * 64);
    float2 sv[RR];
#pragma unroll
    for (int r = 0; r < RR; r++) {
        sv[r] = *(const float2*)&srow[r * 64 + f0];
        s_s[w][r * 64 + f0] = sv[r].x;
        s_s[w][r * 64 + f0 + 1] = sv[r].y;
    }
    __syncwarp();

    // aux logits
#pragma unroll
    for (int r = 0; r < RR; r++) {
        float p = sv[r].x * __ldg(&aw[r * 64 + f0]) + sv[r].y * __ldg(&aw[r * 64 + f0 + 1]);
        p = wsum(p);
        if (l == 0) out[NN + (size_t)node * RR + r] = p + __ldg(&ab[r]);
    }

    // gate MLP per relation
    float g[RR];
    float b0 = __ldg(&gb1[f0]), b1 = __ldg(&gb1[f0 + 1]);
    float w20 = __ldg(&gw2[f0]), w21 = __ldg(&gw2[f0 + 1]);
    float gb2v = __ldg(&gb2[0]);
#pragma unroll
    for (int r = 0; r < RR; r++) {
        float t0 = b0, t1 = b1;
        const float* sr = &s_s[w][r * 64];
#pragma unroll 8
        for (int i = 0; i < 64; i++) {
            float si = sr[i];
            float2 wv = *(const float2*)&gw1[i * 64 + f0];
            t0 = fmaf(si, wv.x, t0);
            t1 = fmaf(si, wv.y, t1);
        }
        float gp = fmaxf(t0, 0.f) * w20 + fmaxf(t1, 0.f) * w21;
        g[r] = wsum(gp) + gb2v;
    }

    // softmax over relations, fused embedding
    float m = g[0];
#pragma unroll
    for (int r = 1; r < RR; r++) m = fmaxf(m, g[r]);
    float es = 0.f, e[RR];
#pragma unroll
    for (int r = 0; r < RR; r++) { e[r] = expf(g[r] - m); es += e[r]; }
    float inv = 1.0f / es;
    float fx = 0.f, fy = 0.f;
#pragma unroll
    for (int r = 0; r < RR; r++) {
        float a = e[r] * inv;
        fx = fmaf(a, sv[r].x, fx);
        fy = fmaf(a, sv[r].y, fy);
    }
    s_t[w][f0] = fx; s_t[w][f0 + 1] = fy;
    __syncwarp();

    // proj
    float t0 = __ldg(&pb[f0]), t1 = __ldg(&pb[f0 + 1]);
#pragma unroll 8
    for (int i = 0; i < 64; i++) {
        float fi = s_t[w][i];
        float2 wv = *(const float2*)&pw[i * 64 + f0];
        t0 = fmaf(fi, wv.x, t0);
        t1 = fmaf(fi, wv.y, t1);
    }
    float hp0 = fmaxf(t0, 0.f), hp1 = fmaxf(t1, 0.f);
    __syncwarp();
    s_t[w][f0] = hp0; s_t[w][f0 + 1] = hp1;
    __syncwarp();

    // cls layer 1 + output dot
    t0 = __ldg(&cb1[f0]); t1 = __ldg(&cb1[f0 + 1]);
#pragma unroll 8
    for (int i = 0; i < 64; i++) {
        float hi = s_t[w][i];
        float2 wv = *(const float2*)&cw1[i * 64 + f0];
        t0 = fmaf(hi, wv.x, t0);
        t1 = fmaf(hi, wv.y, t1);
    }
    float c0 = fmaxf(t0, 0.f), c1 = fmaxf(t1, 0.f);
    float lp = c0 * __ldg(&cw2[f0]) + c1 * __ldg(&cw2[f0 + 1]);
    lp = wsum(lp);
    if (l == 0) out[node] = lp + __ldg(&cb2[0]);
}

// ---------------- launch ----------------
extern "C" void kernel_launch(void* const* d_in, const int* in_sizes, int n_in,
                              void* d_out, int out_size) {
    const float* x       = (const float*)d_in[0];
    const int*   ei      = (const int*)d_in[1];
    const float* cheb1_w = (const float*)d_in[2];
    const float* cheb1_b = (const float*)d_in[3];
    const float* cheb2_w = (const float*)d_in[4];
    const float* cheb2_b = (const float*)d_in[5];
    const float* gate_w1 = (const float*)d_in[6];
    const float* gate_b1 = (const float*)d_in[7];
    const float* gate_w2 = (const float*)d_in[8];
    const float* gate_b2 = (const float*)d_in[9];
    const float* proj_w  = (const float*)d_in[10];
    const float* proj_b  = (const float*)d_in[11];
    const float* cls_w1  = (const float*)d_in[12];
    const float* cls_b1  = (const float*)d_in[13];
    const float* cls_w2  = (const float*)d_in[14];
    const float* cls_b2  = (const float*)d_in[15];
    const float* aux_w   = (const float*)d_in[16];
    const float* aux_b   = (const float*)d_in[17];
    float* out = (float*)d_out;

    // weight prep + CSR build (parallel 3-phase scan)
    k_prep<<<(RR * DIN * 192 + RR * HH * 192 + 255) / 256, 256>>>(cheb1_w, cheb2_w);
    k_zero<<<(RR * NN + 255) / 256, 256>>>();
    k_count<<<(RR * EE + 255) / 256, 256>>>(ei);
    k_part<<<RR * NB, 1024>>>();
    k_mid<<<RR, 128>>>();
    k_rowptr<<<RR * NB, 1024>>>();
    k_scatter<<<(RR * EE + 255) / 256, 256>>>(ei);

    dim3 ggrid1((NN + 63) / 64, RR);
    dim3 sgrid((NN + 7) / 8, RR);

    // layer 1
    k_gemm<DIN, true><<<ggrid1, 128>>>(x);
    k_spmm<0><<<sgrid, 256>>>(nullptr);
    k_spmm<1><<<sgrid, 256>>>(cheb1_b);
    // layer 2
    k_gemm<HH, false><<<ggrid1, 128>>>(nullptr);
    k_spmm<0><<<sgrid, 256>>>(nullptr);
    k_spmm<2><<<sgrid, 256>>>(cheb2_b);
    // fusion + heads
    k_final<<<(NN + 7) / 8, 256>>>(gate_w1, gate_b1, gate_w2, gate_b2,
                                   proj_w, proj_b, cls_w1, cls_b1, cls_w2, cls_b2,
                                   aux_w, aux_b, out);
}